// round 15
// baseline (speedup 1.0000x reference)
#include <cuda_runtime.h>
#include <cuda_fp16.h>
#include <cuda_bf16.h>
#include <cstdint>

#define USER_NUM 100000
#define ITEM_NUM 50000
#define N_NODES  (USER_NUM + ITEM_NUM)   // 150000
#define EMB      64
#define TOT      (N_NODES * EMB)         // 9,600,000 elements
#define USER_ELEMS (USER_NUM * EMB)
#define NNZ_MAX  4800000
#define SCAN_CHUNK 1024
#define NCHUNK   ((N_NODES + SCAN_CHUNK - 1) / SCAN_CHUNK)   // 147

// Edge record: (col << 14) | m, where val ≈ m * 2^-19  (vals < 1/32 = 2^-5,
// so m = round(val * 2^19) < 16384 fits 14 bits; col < 150000 < 2^18).
#define VAL_SCALE   524288.0f            // 2^19
#define VAL_INV     (1.0f / 524288.0f)

// Static device scratch (no runtime allocation allowed)
__device__ __half g_ego[TOT];            // fp16 copy of concat(user,item)
__device__ __half g_h1[TOT];             // layer-1 output (fp16)
__device__ __half g_h2[TOT];             // layer-2 output (fp16)
__device__ int   g_rowptr[N_NODES + 1];
__device__ int   g_cursor[N_NODES];
__device__ int   g_counts[N_NODES];
__device__ __align__(16) uint32_t g_edges[NNZ_MAX];  // packed 4B, row-sorted
__device__ int   g_partial[256];

// ---------------------------------------------------------------------------
// zero the row histogram
// ---------------------------------------------------------------------------
__global__ void zero_counts(int* __restrict__ counts) {
    int i = blockIdx.x * blockDim.x + threadIdx.x;
    if (i < N_NODES) counts[i] = 0;
}

// ---------------------------------------------------------------------------
// FUSED: convert ego -> fp16  +  per-row histogram. 1 edge/thread (max TLP
// for the atomics — R11 lesson: never batch atomics per thread).
// ---------------------------------------------------------------------------
__global__ void conv_hist(const float2* __restrict__ user2,
                          const float2* __restrict__ item2,
                          __half2* __restrict__ ego2,
                          const int* __restrict__ row,
                          int* __restrict__ counts, int nnz) {
    int i = blockIdx.x * blockDim.x + threadIdx.x;
    if (i < TOT / 2) {
        float2 v = (i < USER_ELEMS / 2) ? __ldg(user2 + i)
                                        : __ldg(item2 + (i - USER_ELEMS / 2));
        ego2[i] = __floats2half2_rn(v.x, v.y);
    }
    if (i < nnz) atomicAdd(&counts[__ldcs(row + i)], 1);
}

// ---------------------------------------------------------------------------
// Scan stage 1: per-chunk sums (147 partials)
// ---------------------------------------------------------------------------
__global__ void scan_reduce(const int* __restrict__ counts,
                            int* __restrict__ partial) {
    __shared__ int s[SCAN_CHUNK];
    int i = blockIdx.x * SCAN_CHUNK + threadIdx.x;
    s[threadIdx.x] = (i < N_NODES) ? counts[i] : 0;
    __syncthreads();
    for (int st = SCAN_CHUNK / 2; st > 0; st >>= 1) {
        if (threadIdx.x < st) s[threadIdx.x] += s[threadIdx.x + st];
        __syncthreads();
    }
    if (threadIdx.x == 0) partial[blockIdx.x] = s[0];
}

// ---------------------------------------------------------------------------
// Scan stage 2 (fused): every block redundantly scans the partials in smem,
// then does its chunk's exclusive scan -> rowptr, cursor.
// ---------------------------------------------------------------------------
__global__ void scan_final(const int* __restrict__ counts,
                           const int* __restrict__ partial,
                           int* __restrict__ rowptr,
                           int* __restrict__ cursor, int nnz) {
    __shared__ int sp[256];
    __shared__ int s[SCAN_CHUNK];

    if (threadIdx.x < 256) {
        int v = (threadIdx.x < NCHUNK) ? partial[threadIdx.x] : 0;
        sp[threadIdx.x] = v;
    }
    __syncthreads();
    for (int st = 1; st < 256; st <<= 1) {
        int t = 0;
        if (threadIdx.x < 256 && threadIdx.x >= st) t = sp[threadIdx.x - st];
        __syncthreads();
        if (threadIdx.x < 256) sp[threadIdx.x] += t;
        __syncthreads();
    }
    int block_ex = (blockIdx.x == 0) ? 0 : sp[blockIdx.x - 1];

    int i = blockIdx.x * SCAN_CHUNK + threadIdx.x;
    int v = (i < N_NODES) ? counts[i] : 0;
    s[threadIdx.x] = v;
    __syncthreads();
    for (int st = 1; st < SCAN_CHUNK; st <<= 1) {
        int t = (threadIdx.x >= st) ? s[threadIdx.x - st] : 0;
        __syncthreads();
        s[threadIdx.x] += t;
        __syncthreads();
    }
    if (i < N_NODES) {
        int ex = block_ex + s[threadIdx.x] - v;
        rowptr[i] = ex;
        cursor[i] = ex;
    }
    if (i == 0) rowptr[N_NODES] = nnz;
}

// ---------------------------------------------------------------------------
// Counting-sort stage 3: scatter packed 4B edges (1 edge/thread, max TLP)
// ---------------------------------------------------------------------------
__global__ void scatter_kernel(const int* __restrict__ row,
                               const int* __restrict__ col,
                               const float* __restrict__ vals,
                               int* __restrict__ cursor,
                               uint32_t* __restrict__ edges, int nnz) {
    int i = blockIdx.x * blockDim.x + threadIdx.x;
    if (i < nnz) {
        int r = __ldcs(row + i);
        int p = atomicAdd(&cursor[r], 1);
        float v = __ldcs(vals + i);
        uint32_t m = __float2uint_rn(v * VAL_SCALE);
        if (m > 16383u) m = 16383u;      // safety clamp (vals < 1/32)
        uint32_t c = (uint32_t)__ldcs(col + i);
        edges[p] = (c << 14) | m;
    }
}

// ---------------------------------------------------------------------------
// CSR SpMM, warp per row, fp16 gather (128 B/edge), fp32 accumulation.
// Edge metadata: ONE warp-uniform uint4 = FOUR packed edges (0.25 meta
// wavefronts/edge; R14's int4=2-edge config proved this axis pays).
// Gather pattern byte-identical to the proven config (lane owns a __half2,
// 4 gathers in flight).
// FINAL=false: y[row] = h (fp16)
// FINAL=true : out[row] = (ego + h1 + h2 + h) * 0.25  (fp32), no y store
// ---------------------------------------------------------------------------
template<bool FINAL>
__global__ void __launch_bounds__(256, 8)
spmm_csr(const int* __restrict__ rowptr,
         const uint32_t* __restrict__ edges,
         const __half* __restrict__ x,     // gather source
         __half* __restrict__ y,           // !FINAL
         const __half* __restrict__ ego,   // FINAL
         const __half* __restrict__ h1,    // FINAL
         float* __restrict__ out) {        // FINAL
    int warp = (blockIdx.x * blockDim.x + threadIdx.x) >> 5;
    int lane = threadIdx.x & 31;
    if (warp >= N_NODES) return;

    int start = __ldg(rowptr + warp);
    int end   = __ldg(rowptr + warp + 1);

    float ax = 0.f, ay = 0.f;

    #define XR(c) (reinterpret_cast<const __half2*>(x + (size_t)(c) * EMB) + lane)
    #define ACC_REC(rec_) do {                                            \
        uint32_t c_ = (rec_) >> 14;                                       \
        float v_ = (float)((rec_) & 16383u) * VAL_INV;                    \
        float2 xv_ = __half22float2(__ldg(XR(c_)));                       \
        ax = fmaf(v_, xv_.x, ax);                                         \
        ay = fmaf(v_, xv_.y, ay);                                         \
    } while (0)

    int e = start;
    // align to 4-edge boundary for 16B uint4 loads
    while ((e & 3) && e < end) {
        ACC_REC(__ldg(edges + e));
        e++;
    }

    // 4 edges per iter via ONE warp-uniform uint4 load; 4 gathers in flight
    for (; e + 4 <= end; e += 4) {
        uint4 q = __ldg(reinterpret_cast<const uint4*>(edges + e));
        uint32_t c0 = q.x >> 14, c1 = q.y >> 14, c2 = q.z >> 14, c3 = q.w >> 14;
        float v0 = (float)(q.x & 16383u) * VAL_INV;
        float v1 = (float)(q.y & 16383u) * VAL_INV;
        float v2 = (float)(q.z & 16383u) * VAL_INV;
        float v3 = (float)(q.w & 16383u) * VAL_INV;
        float2 x0 = __half22float2(__ldg(XR(c0)));
        float2 x1 = __half22float2(__ldg(XR(c1)));
        float2 x2 = __half22float2(__ldg(XR(c2)));
        float2 x3 = __half22float2(__ldg(XR(c3)));
        ax = fmaf(v0, x0.x, ax);
        ay = fmaf(v0, x0.y, ay);
        ax = fmaf(v1, x1.x, ax);
        ay = fmaf(v1, x1.y, ay);
        ax = fmaf(v2, x2.x, ax);
        ay = fmaf(v2, x2.y, ay);
        ax = fmaf(v3, x3.x, ax);
        ay = fmaf(v3, x3.y, ay);
    }
    // tail (up to 3 edges)
    for (; e < end; ++e) {
        ACC_REC(__ldg(edges + e));
    }
    #undef ACC_REC
    #undef XR

    if (!FINAL) {
        reinterpret_cast<__half2*>(y + (size_t)warp * EMB)[lane] =
            __floats2half2_rn(ax, ay);
    } else {
        float2 eg = __half22float2(
            __ldg(reinterpret_cast<const __half2*>(ego + (size_t)warp * EMB) + lane));
        float2 a1 = __half22float2(
            __ldg(reinterpret_cast<const __half2*>(h1 + (size_t)warp * EMB) + lane));
        float2 a2 = __half22float2(
            __ldg(reinterpret_cast<const __half2*>(x + (size_t)warp * EMB) + lane));
        float2 o;
        o.x = (eg.x + a1.x + a2.x + ax) * 0.25f;
        o.y = (eg.y + a1.y + a2.y + ay) * 0.25f;
        reinterpret_cast<float2*>(out + (size_t)warp * EMB)[lane] = o;
    }
}

extern "C" void kernel_launch(void* const* d_in, const int* in_sizes, int n_in,
                              void* d_out, int out_size) {
    const float* user_emb = (const float*)d_in[0];
    const float* item_emb = (const float*)d_in[1];
    const int*   adj_row  = (const int*)  d_in[2];
    const int*   adj_col  = (const int*)  d_in[3];
    const float* adj_vals = (const float*)d_in[4];
    float* out = (float*)d_out;
    int nnz = in_sizes[2];

    __half* ego;   cudaGetSymbolAddress((void**)&ego,    g_ego);
    __half* h1;    cudaGetSymbolAddress((void**)&h1,     g_h1);
    __half* h2;    cudaGetSymbolAddress((void**)&h2,     g_h2);
    int*   rowptr; cudaGetSymbolAddress((void**)&rowptr, g_rowptr);
    int*   cursor; cudaGetSymbolAddress((void**)&cursor, g_cursor);
    int*   counts; cudaGetSymbolAddress((void**)&counts, g_counts);
    uint32_t* edges; cudaGetSymbolAddress((void**)&edges, g_edges);
    int*   partial;cudaGetSymbolAddress((void**)&partial,g_partial);

    const int T = 256;
    const int ZC_BLOCKS = (N_NODES + T - 1) / T;
    const int CH_BLOCKS = ((TOT / 2 > nnz ? TOT / 2 : nnz) + T - 1) / T;
    const int EG_BLOCKS = (nnz + T - 1) / T;
    const int SP_BLOCKS = (N_NODES * 32 + T - 1) / T;    // warp per row

    zero_counts<<<ZC_BLOCKS, T>>>(counts);
    conv_hist<<<CH_BLOCKS, T>>>((const float2*)user_emb, (const float2*)item_emb,
                                (__half2*)ego, adj_row, counts, nnz);
    scan_reduce<<<NCHUNK, SCAN_CHUNK>>>(counts, partial);
    scan_final<<<NCHUNK, SCAN_CHUNK>>>(counts, partial, rowptr, cursor, nnz);
    scatter_kernel<<<EG_BLOCKS, T>>>(adj_row, adj_col, adj_vals, cursor, edges, nnz);

    // layer 1: h1 = A*ego
    spmm_csr<false><<<SP_BLOCKS, T>>>(rowptr, edges, ego, h1, nullptr, nullptr, nullptr);
    // layer 2: h2 = A*h1
    spmm_csr<false><<<SP_BLOCKS, T>>>(rowptr, edges, h1, h2, nullptr, nullptr, nullptr);
    // layer 3: out = (ego + h1 + h2 + A*h2) / 4
    spmm_csr<true><<<SP_BLOCKS, T>>>(rowptr, edges, h2, nullptr, ego, h1, out);
}

// round 16
// speedup vs baseline: 1.4496x; 1.4496x over previous
#include <cuda_runtime.h>
#include <cuda_fp16.h>
#include <cuda_bf16.h>
#include <cstdint>

#define USER_NUM 100000
#define ITEM_NUM 50000
#define N_NODES  (USER_NUM + ITEM_NUM)   // 150000
#define EMB      64
#define TOT      (N_NODES * EMB)         // 9,600,000 elements
#define USER_ELEMS (USER_NUM * EMB)
#define NNZ_MAX  4800000
#define SCAN_CHUNK 1024
#define NCHUNK   ((N_NODES + SCAN_CHUNK - 1) / SCAN_CHUNK)   // 147

// Edge record: (col << 14) | m, where val ≈ m * 2^-19  (vals < 1/32 = 2^-5,
// so m = round(val * 2^19) < 16384 fits 14 bits; col < 150000 < 2^18).
// Decode WITHOUT I2F (slow conversion pipe — R15 lesson):
//   asfloat((m & 0x3FFF) | 0x4B000000) = 2^23 + m   (LOP3)
//   v = fma(that, 2^-19, -2^23 * 2^-19 = -16.0f)    (FFMA)
#define VAL_SCALE   524288.0f            // 2^19
#define VAL_INV     (1.0f / 524288.0f)
#define MAGIC_EXP   0x4B000000u          // float 2^23
#define MAGIC_OFF   (-16.0f)             // -(2^23) * 2^-19

// Static device scratch (no runtime allocation allowed)
__device__ __half g_ego[TOT];            // fp16 copy of concat(user,item)
__device__ __half g_h1[TOT];             // layer-1 output (fp16)
__device__ __half g_h2[TOT];             // layer-2 output (fp16)
__device__ int   g_rowptr[N_NODES + 1];
__device__ int   g_cursor[N_NODES];
__device__ int   g_counts[N_NODES];
__device__ __align__(16) uint32_t g_edges[NNZ_MAX];  // packed 4B, row-sorted
__device__ int   g_partial[256];

__device__ __forceinline__ float decode_val(uint32_t rec) {
    uint32_t bits = (rec & 16383u) | MAGIC_EXP;      // LOP3
    return fmaf(__uint_as_float(bits), VAL_INV, MAGIC_OFF);  // FFMA
}

// ---------------------------------------------------------------------------
// zero the row histogram
// ---------------------------------------------------------------------------
__global__ void zero_counts(int* __restrict__ counts) {
    int i = blockIdx.x * blockDim.x + threadIdx.x;
    if (i < N_NODES) counts[i] = 0;
}

// ---------------------------------------------------------------------------
// FUSED: convert ego -> fp16  +  per-row histogram. 1 edge/thread (max TLP
// for the atomics — R11 lesson: never batch atomics per thread).
// ---------------------------------------------------------------------------
__global__ void conv_hist(const float2* __restrict__ user2,
                          const float2* __restrict__ item2,
                          __half2* __restrict__ ego2,
                          const int* __restrict__ row,
                          int* __restrict__ counts, int nnz) {
    int i = blockIdx.x * blockDim.x + threadIdx.x;
    if (i < TOT / 2) {
        float2 v = (i < USER_ELEMS / 2) ? __ldg(user2 + i)
                                        : __ldg(item2 + (i - USER_ELEMS / 2));
        ego2[i] = __floats2half2_rn(v.x, v.y);
    }
    if (i < nnz) atomicAdd(&counts[__ldcs(row + i)], 1);
}

// ---------------------------------------------------------------------------
// Scan stage 1: per-chunk sums (147 partials)
// ---------------------------------------------------------------------------
__global__ void scan_reduce(const int* __restrict__ counts,
                            int* __restrict__ partial) {
    __shared__ int s[SCAN_CHUNK];
    int i = blockIdx.x * SCAN_CHUNK + threadIdx.x;
    s[threadIdx.x] = (i < N_NODES) ? counts[i] : 0;
    __syncthreads();
    for (int st = SCAN_CHUNK / 2; st > 0; st >>= 1) {
        if (threadIdx.x < st) s[threadIdx.x] += s[threadIdx.x + st];
        __syncthreads();
    }
    if (threadIdx.x == 0) partial[blockIdx.x] = s[0];
}

// ---------------------------------------------------------------------------
// Scan stage 2 (fused): every block redundantly scans the partials in smem,
// then does its chunk's exclusive scan -> rowptr, cursor.
// ---------------------------------------------------------------------------
__global__ void scan_final(const int* __restrict__ counts,
                           const int* __restrict__ partial,
                           int* __restrict__ rowptr,
                           int* __restrict__ cursor, int nnz) {
    __shared__ int sp[256];
    __shared__ int s[SCAN_CHUNK];

    if (threadIdx.x < 256) {
        int v = (threadIdx.x < NCHUNK) ? partial[threadIdx.x] : 0;
        sp[threadIdx.x] = v;
    }
    __syncthreads();
    for (int st = 1; st < 256; st <<= 1) {
        int t = 0;
        if (threadIdx.x < 256 && threadIdx.x >= st) t = sp[threadIdx.x - st];
        __syncthreads();
        if (threadIdx.x < 256) sp[threadIdx.x] += t;
        __syncthreads();
    }
    int block_ex = (blockIdx.x == 0) ? 0 : sp[blockIdx.x - 1];

    int i = blockIdx.x * SCAN_CHUNK + threadIdx.x;
    int v = (i < N_NODES) ? counts[i] : 0;
    s[threadIdx.x] = v;
    __syncthreads();
    for (int st = 1; st < SCAN_CHUNK; st <<= 1) {
        int t = (threadIdx.x >= st) ? s[threadIdx.x - st] : 0;
        __syncthreads();
        s[threadIdx.x] += t;
        __syncthreads();
    }
    if (i < N_NODES) {
        int ex = block_ex + s[threadIdx.x] - v;
        rowptr[i] = ex;
        cursor[i] = ex;
    }
    if (i == 0) rowptr[N_NODES] = nnz;
}

// ---------------------------------------------------------------------------
// Counting-sort stage 3: scatter packed 4B edges (1 edge/thread, max TLP)
// (the single I2F->F2I here runs once per edge in preproc, not per layer)
// ---------------------------------------------------------------------------
__global__ void scatter_kernel(const int* __restrict__ row,
                               const int* __restrict__ col,
                               const float* __restrict__ vals,
                               int* __restrict__ cursor,
                               uint32_t* __restrict__ edges, int nnz) {
    int i = blockIdx.x * blockDim.x + threadIdx.x;
    if (i < nnz) {
        int r = __ldcs(row + i);
        int p = atomicAdd(&cursor[r], 1);
        float v = __ldcs(vals + i);
        uint32_t m = __float2uint_rn(v * VAL_SCALE);
        if (m > 16383u) m = 16383u;      // safety clamp (vals < 1/32)
        uint32_t c = (uint32_t)__ldcs(col + i);
        edges[p] = (c << 14) | m;
    }
}

// ---------------------------------------------------------------------------
// CSR SpMM, warp per row, fp16 gather (128 B/edge), fp32 accumulation.
// Edge metadata: ONE warp-uniform uint4 = FOUR packed edges. Value decode is
// LOP3+FFMA (full-rate) — NO I2F (R15's regression was the conversion pipe).
// Gather pattern byte-identical to the proven config.
// FINAL=false: y[row] = h (fp16)
// FINAL=true : out[row] = (ego + h1 + h2 + h) * 0.25  (fp32), no y store
// ---------------------------------------------------------------------------
template<bool FINAL>
__global__ void __launch_bounds__(256, 8)
spmm_csr(const int* __restrict__ rowptr,
         const uint32_t* __restrict__ edges,
         const __half* __restrict__ x,     // gather source
         __half* __restrict__ y,           // !FINAL
         const __half* __restrict__ ego,   // FINAL
         const __half* __restrict__ h1,    // FINAL
         float* __restrict__ out) {        // FINAL
    int warp = (blockIdx.x * blockDim.x + threadIdx.x) >> 5;
    int lane = threadIdx.x & 31;
    if (warp >= N_NODES) return;

    int start = __ldg(rowptr + warp);
    int end   = __ldg(rowptr + warp + 1);

    float ax = 0.f, ay = 0.f;

    #define XR(c) (reinterpret_cast<const __half2*>(x + (size_t)(c) * EMB) + lane)
    #define ACC_REC(rec_) do {                                            \
        uint32_t c_ = (rec_) >> 14;                                       \
        float v_ = decode_val(rec_);                                      \
        float2 xv_ = __half22float2(__ldg(XR(c_)));                       \
        ax = fmaf(v_, xv_.x, ax);                                         \
        ay = fmaf(v_, xv_.y, ay);                                         \
    } while (0)

    int e = start;
    // align to 4-edge boundary for 16B uint4 loads
    while ((e & 3) && e < end) {
        ACC_REC(__ldg(edges + e));
        e++;
    }

    // 4 edges per iter via ONE warp-uniform uint4 load; 4 gathers in flight
    for (; e + 4 <= end; e += 4) {
        uint4 q = __ldg(reinterpret_cast<const uint4*>(edges + e));
        uint32_t c0 = q.x >> 14, c1 = q.y >> 14, c2 = q.z >> 14, c3 = q.w >> 14;
        float v0 = decode_val(q.x);
        float v1 = decode_val(q.y);
        float v2 = decode_val(q.z);
        float v3 = decode_val(q.w);
        float2 x0 = __half22float2(__ldg(XR(c0)));
        float2 x1 = __half22float2(__ldg(XR(c1)));
        float2 x2 = __half22float2(__ldg(XR(c2)));
        float2 x3 = __half22float2(__ldg(XR(c3)));
        ax = fmaf(v0, x0.x, ax);
        ay = fmaf(v0, x0.y, ay);
        ax = fmaf(v1, x1.x, ax);
        ay = fmaf(v1, x1.y, ay);
        ax = fmaf(v2, x2.x, ax);
        ay = fmaf(v2, x2.y, ay);
        ax = fmaf(v3, x3.x, ax);
        ay = fmaf(v3, x3.y, ay);
    }
    // tail (up to 3 edges)
    for (; e < end; ++e) {
        ACC_REC(__ldg(edges + e));
    }
    #undef ACC_REC
    #undef XR

    if (!FINAL) {
        reinterpret_cast<__half2*>(y + (size_t)warp * EMB)[lane] =
            __floats2half2_rn(ax, ay);
    } else {
        float2 eg = __half22float2(
            __ldg(reinterpret_cast<const __half2*>(ego + (size_t)warp * EMB) + lane));
        float2 a1 = __half22float2(
            __ldg(reinterpret_cast<const __half2*>(h1 + (size_t)warp * EMB) + lane));
        float2 a2 = __half22float2(
            __ldg(reinterpret_cast<const __half2*>(x + (size_t)warp * EMB) + lane));
        float2 o;
        o.x = (eg.x + a1.x + a2.x + ax) * 0.25f;
        o.y = (eg.y + a1.y + a2.y + ay) * 0.25f;
        reinterpret_cast<float2*>(out + (size_t)warp * EMB)[lane] = o;
    }
}

extern "C" void kernel_launch(void* const* d_in, const int* in_sizes, int n_in,
                              void* d_out, int out_size) {
    const float* user_emb = (const float*)d_in[0];
    const float* item_emb = (const float*)d_in[1];
    const int*   adj_row  = (const int*)  d_in[2];
    const int*   adj_col  = (const int*)  d_in[3];
    const float* adj_vals = (const float*)d_in[4];
    float* out = (float*)d_out;
    int nnz = in_sizes[2];

    __half* ego;   cudaGetSymbolAddress((void**)&ego,    g_ego);
    __half* h1;    cudaGetSymbolAddress((void**)&h1,     g_h1);
    __half* h2;    cudaGetSymbolAddress((void**)&h2,     g_h2);
    int*   rowptr; cudaGetSymbolAddress((void**)&rowptr, g_rowptr);
    int*   cursor; cudaGetSymbolAddress((void**)&cursor, g_cursor);
    int*   counts; cudaGetSymbolAddress((void**)&counts, g_counts);
    uint32_t* edges; cudaGetSymbolAddress((void**)&edges, g_edges);
    int*   partial;cudaGetSymbolAddress((void**)&partial,g_partial);

    const int T = 256;
    const int ZC_BLOCKS = (N_NODES + T - 1) / T;
    const int CH_BLOCKS = ((TOT / 2 > nnz ? TOT / 2 : nnz) + T - 1) / T;
    const int EG_BLOCKS = (nnz + T - 1) / T;
    const int SP_BLOCKS = (N_NODES * 32 + T - 1) / T;    // warp per row

    zero_counts<<<ZC_BLOCKS, T>>>(counts);
    conv_hist<<<CH_BLOCKS, T>>>((const float2*)user_emb, (const float2*)item_emb,
                                (__half2*)ego, adj_row, counts, nnz);
    scan_reduce<<<NCHUNK, SCAN_CHUNK>>>(counts, partial);
    scan_final<<<NCHUNK, SCAN_CHUNK>>>(counts, partial, rowptr, cursor, nnz);
    scatter_kernel<<<EG_BLOCKS, T>>>(adj_row, adj_col, adj_vals, cursor, edges, nnz);

    // layer 1: h1 = A*ego
    spmm_csr<false><<<SP_BLOCKS, T>>>(rowptr, edges, ego, h1, nullptr, nullptr, nullptr);
    // layer 2: h2 = A*h1
    spmm_csr<false><<<SP_BLOCKS, T>>>(rowptr, edges, h1, h2, nullptr, nullptr, nullptr);
    // layer 3: out = (ego + h1 + h2 + A*h2) / 4
    spmm_csr<true><<<SP_BLOCKS, T>>>(rowptr, edges, h2, nullptr, ego, h1, out);
}

// round 17
// speedup vs baseline: 1.6079x; 1.1092x over previous
#include <cuda_runtime.h>
#include <cuda_fp16.h>
#include <cuda_bf16.h>
#include <cstdint>

#define USER_NUM 100000
#define ITEM_NUM 50000
#define N_NODES  (USER_NUM + ITEM_NUM)   // 150000
#define EMB      64
#define TOT      (N_NODES * EMB)         // 9,600,000 elements
#define USER_ELEMS (USER_NUM * EMB)
#define NNZ_MAX  4800000
#define SCAN_CHUNK 1024
#define NCHUNK   ((N_NODES + SCAN_CHUNK - 1) / SCAN_CHUNK)   // 147

// Static device scratch (no runtime allocation allowed)
__device__ __half g_ego[TOT];            // fp16 copy of concat(user,item)
__device__ __half g_h1[TOT];             // layer-1 output (fp16)
__device__ __half g_h2[TOT];             // layer-2 output (fp16)
__device__ int   g_rowptr[N_NODES + 1];
__device__ int   g_cursor[N_NODES];
__device__ int   g_counts[N_NODES];
__device__ __align__(16) int2 g_edges[NNZ_MAX];  // (col, val-bits), row-sorted
__device__ int   g_partial[256];

// ---------------------------------------------------------------------------
// zero the row histogram
// ---------------------------------------------------------------------------
__global__ void zero_counts(int* __restrict__ counts) {
    int i = blockIdx.x * blockDim.x + threadIdx.x;
    if (i < N_NODES) counts[i] = 0;
}

// ---------------------------------------------------------------------------
// FUSED: convert ego -> fp16  +  per-row histogram. 1 edge/thread (max TLP
// for the atomics — R11 lesson). Row array read with DEFAULT caching (not
// __ldcs): scatter_kernel re-reads it two launches later, so keeping the
// 19.2 MB in L2 turns those reads into L2 hits.
// ---------------------------------------------------------------------------
__global__ void conv_hist(const float2* __restrict__ user2,
                          const float2* __restrict__ item2,
                          __half2* __restrict__ ego2,
                          const int* __restrict__ row,
                          int* __restrict__ counts, int nnz) {
    int i = blockIdx.x * blockDim.x + threadIdx.x;
    if (i < TOT / 2) {
        float2 v = (i < USER_ELEMS / 2) ? __ldg(user2 + i)
                                        : __ldg(item2 + (i - USER_ELEMS / 2));
        ego2[i] = __floats2half2_rn(v.x, v.y);
    }
    if (i < nnz) atomicAdd(&counts[__ldg(row + i)], 1);
}

// ---------------------------------------------------------------------------
// Scan stage 1: per-chunk sums (147 partials)
// ---------------------------------------------------------------------------
__global__ void scan_reduce(const int* __restrict__ counts,
                            int* __restrict__ partial) {
    __shared__ int s[SCAN_CHUNK];
    int i = blockIdx.x * SCAN_CHUNK + threadIdx.x;
    s[threadIdx.x] = (i < N_NODES) ? counts[i] : 0;
    __syncthreads();
    for (int st = SCAN_CHUNK / 2; st > 0; st >>= 1) {
        if (threadIdx.x < st) s[threadIdx.x] += s[threadIdx.x + st];
        __syncthreads();
    }
    if (threadIdx.x == 0) partial[blockIdx.x] = s[0];
}

// ---------------------------------------------------------------------------
// Scan stage 2 (fused): every block redundantly scans the partials in smem,
// then does its chunk's exclusive scan -> rowptr, cursor.
// ---------------------------------------------------------------------------
__global__ void scan_final(const int* __restrict__ counts,
                           const int* __restrict__ partial,
                           int* __restrict__ rowptr,
                           int* __restrict__ cursor, int nnz) {
    __shared__ int sp[256];
    __shared__ int s[SCAN_CHUNK];

    if (threadIdx.x < 256) {
        int v = (threadIdx.x < NCHUNK) ? partial[threadIdx.x] : 0;
        sp[threadIdx.x] = v;
    }
    __syncthreads();
    for (int st = 1; st < 256; st <<= 1) {
        int t = 0;
        if (threadIdx.x < 256 && threadIdx.x >= st) t = sp[threadIdx.x - st];
        __syncthreads();
        if (threadIdx.x < 256) sp[threadIdx.x] += t;
        __syncthreads();
    }
    int block_ex = (blockIdx.x == 0) ? 0 : sp[blockIdx.x - 1];

    int i = blockIdx.x * SCAN_CHUNK + threadIdx.x;
    int v = (i < N_NODES) ? counts[i] : 0;
    s[threadIdx.x] = v;
    __syncthreads();
    for (int st = 1; st < SCAN_CHUNK; st <<= 1) {
        int t = (threadIdx.x >= st) ? s[threadIdx.x - st] : 0;
        __syncthreads();
        s[threadIdx.x] += t;
        __syncthreads();
    }
    if (i < N_NODES) {
        int ex = block_ex + s[threadIdx.x] - v;
        rowptr[i] = ex;
        cursor[i] = ex;
    }
    if (i == 0) rowptr[N_NODES] = nnz;
}

// ---------------------------------------------------------------------------
// Counting-sort stage 3: scatter edges (1 edge/thread, max TLP for atomics)
// row read hits L2 (warmed by conv_hist); col/vals are single-use -> __ldcs.
// ---------------------------------------------------------------------------
__global__ void scatter_kernel(const int* __restrict__ row,
                               const int* __restrict__ col,
                               const float* __restrict__ vals,
                               int* __restrict__ cursor,
                               int2* __restrict__ edges, int nnz) {
    int i = blockIdx.x * blockDim.x + threadIdx.x;
    if (i < nnz) {
        int r = __ldg(row + i);
        int p = atomicAdd(&cursor[r], 1);
        edges[p] = make_int2(__ldcs(col + i), __float_as_int(__ldcs(vals + i)));
    }
}

// ---------------------------------------------------------------------------
// CSR SpMM, warp per row, fp16 gather (128 B/edge), fp32 accumulation.
// R14-proven body: edge metadata via warp-uniform int4 (2 edges per LDG,
// value bits used directly — no decode chain), gather lane owns a __half2,
// 4 gathers in flight. DO NOT CHANGE (unroll-8, half-warp pairing, 4B
// packed records all regressed).
// FINAL=false: y[row] = h (fp16)
// FINAL=true : out[row] = (ego + h1 + h2 + h) * 0.25  (fp32), no y store
// ---------------------------------------------------------------------------
template<bool FINAL>
__global__ void __launch_bounds__(256, 8)
spmm_csr(const int* __restrict__ rowptr,
         const int2* __restrict__ edges,
         const __half* __restrict__ x,     // gather source
         __half* __restrict__ y,           // !FINAL
         const __half* __restrict__ ego,   // FINAL
         const __half* __restrict__ h1,    // FINAL
         float* __restrict__ out) {        // FINAL
    int warp = (blockIdx.x * blockDim.x + threadIdx.x) >> 5;
    int lane = threadIdx.x & 31;
    if (warp >= N_NODES) return;

    int start = __ldg(rowptr + warp);
    int end   = __ldg(rowptr + warp + 1);

    float ax = 0.f, ay = 0.f;

    #define XR(c) (reinterpret_cast<const __half2*>(x + (size_t)(c) * EMB) + lane)
    #define ACC_EDGE(col_, vbits_) do {                                   \
        float2 xv_ = __half22float2(__ldg(XR(col_)));                     \
        float v_ = __int_as_float(vbits_);                                \
        ax = fmaf(v_, xv_.x, ax);                                         \
        ay = fmaf(v_, xv_.y, ay);                                         \
    } while (0)

    int e = start;
    // align to even index for 16B int4 loads
    if ((e & 1) && e < end) {
        int2 ed = __ldg(edges + e);
        ACC_EDGE(ed.x, ed.y);
        e++;
    }

    // 4 edges per iter via 2 warp-uniform int4 loads; 4 gathers in flight
    for (; e + 4 <= end; e += 4) {
        int4 q0 = __ldg(reinterpret_cast<const int4*>(edges + e));
        int4 q1 = __ldg(reinterpret_cast<const int4*>(edges + e + 2));
        float2 x0 = __half22float2(__ldg(XR(q0.x)));
        float2 x1 = __half22float2(__ldg(XR(q0.z)));
        float2 x2 = __half22float2(__ldg(XR(q1.x)));
        float2 x3 = __half22float2(__ldg(XR(q1.z)));
        ax = fmaf(__int_as_float(q0.y), x0.x, ax);
        ay = fmaf(__int_as_float(q0.y), x0.y, ay);
        ax = fmaf(__int_as_float(q0.w), x1.x, ax);
        ay = fmaf(__int_as_float(q0.w), x1.y, ay);
        ax = fmaf(__int_as_float(q1.y), x2.x, ax);
        ay = fmaf(__int_as_float(q1.y), x2.y, ay);
        ax = fmaf(__int_as_float(q1.w), x3.x, ax);
        ay = fmaf(__int_as_float(q1.w), x3.y, ay);
    }
    // remaining aligned pair
    if (e + 2 <= end) {
        int4 q0 = __ldg(reinterpret_cast<const int4*>(edges + e));
        float2 x0 = __half22float2(__ldg(XR(q0.x)));
        float2 x1 = __half22float2(__ldg(XR(q0.z)));
        ax = fmaf(__int_as_float(q0.y), x0.x, ax);
        ay = fmaf(__int_as_float(q0.y), x0.y, ay);
        ax = fmaf(__int_as_float(q0.w), x1.x, ax);
        ay = fmaf(__int_as_float(q0.w), x1.y, ay);
        e += 2;
    }
    // trailing edge
    if (e < end) {
        int2 ed = __ldg(edges + e);
        ACC_EDGE(ed.x, ed.y);
    }
    #undef ACC_EDGE
    #undef XR

    if (!FINAL) {
        reinterpret_cast<__half2*>(y + (size_t)warp * EMB)[lane] =
            __floats2half2_rn(ax, ay);
    } else {
        float2 eg = __half22float2(
            __ldg(reinterpret_cast<const __half2*>(ego + (size_t)warp * EMB) + lane));
        float2 a1 = __half22float2(
            __ldg(reinterpret_cast<const __half2*>(h1 + (size_t)warp * EMB) + lane));
        float2 a2 = __half22float2(
            __ldg(reinterpret_cast<const __half2*>(x + (size_t)warp * EMB) + lane));
        float2 o;
        o.x = (eg.x + a1.x + a2.x + ax) * 0.25f;
        o.y = (eg.y + a1.y + a2.y + ay) * 0.25f;
        reinterpret_cast<float2*>(out + (size_t)warp * EMB)[lane] = o;
    }
}

extern "C" void kernel_launch(void* const* d_in, const int* in_sizes, int n_in,
                              void* d_out, int out_size) {
    const float* user_emb = (const float*)d_in[0];
    const float* item_emb = (const float*)d_in[1];
    const int*   adj_row  = (const int*)  d_in[2];
    const int*   adj_col  = (const int*)  d_in[3];
    const float* adj_vals = (const float*)d_in[4];
    float* out = (float*)d_out;
    int nnz = in_sizes[2];

    __half* ego;   cudaGetSymbolAddress((void**)&ego,    g_ego);
    __half* h1;    cudaGetSymbolAddress((void**)&h1,     g_h1);
    __half* h2;    cudaGetSymbolAddress((void**)&h2,     g_h2);
    int*   rowptr; cudaGetSymbolAddress((void**)&rowptr, g_rowptr);
    int*   cursor; cudaGetSymbolAddress((void**)&cursor, g_cursor);
    int*   counts; cudaGetSymbolAddress((void**)&counts, g_counts);
    int2*  edges;  cudaGetSymbolAddress((void**)&edges,  g_edges);
    int*   partial;cudaGetSymbolAddress((void**)&partial,g_partial);

    const int T = 256;
    const int ZC_BLOCKS = (N_NODES + T - 1) / T;
    const int CH_BLOCKS = ((TOT / 2 > nnz ? TOT / 2 : nnz) + T - 1) / T;
    const int EG_BLOCKS = (nnz + T - 1) / T;
    const int SP_BLOCKS = (N_NODES * 32 + T - 1) / T;    // warp per row

    zero_counts<<<ZC_BLOCKS, T>>>(counts);
    conv_hist<<<CH_BLOCKS, T>>>((const float2*)user_emb, (const float2*)item_emb,
                                (__half2*)ego, adj_row, counts, nnz);
    scan_reduce<<<NCHUNK, SCAN_CHUNK>>>(counts, partial);
    scan_final<<<NCHUNK, SCAN_CHUNK>>>(counts, partial, rowptr, cursor, nnz);
    scatter_kernel<<<EG_BLOCKS, T>>>(adj_row, adj_col, adj_vals, cursor, edges, nnz);

    // layer 1: h1 = A*ego
    spmm_csr<false><<<SP_BLOCKS, T>>>(rowptr, edges, ego, h1, nullptr, nullptr, nullptr);
    // layer 2: h2 = A*h1
    spmm_csr<false><<<SP_BLOCKS, T>>>(rowptr, edges, h1, h2, nullptr, nullptr, nullptr);
    // layer 3: out = (ego + h1 + h2 + A*h2) / 4
    spmm_csr<true><<<SP_BLOCKS, T>>>(rowptr, edges, h2, nullptr, ego, h1, out);
}